// round 1
// baseline (speedup 1.0000x reference)
#include <cuda_runtime.h>

#define FULLMASK 0xffffffffu
#define DIN   128
#define HC    256
#define NHEAD 4
#define CH    64
#define NMAX  50016
#define EMAX  900000

// ---------------- scratch (device globals; no allocation allowed) -----------
__device__ float g_h[(size_t)NMAX * HC];    // GEMM output / layer-2 features
__device__ float g_act[(size_t)NMAX * HC];  // layer-1 activations
__device__ float g_asrc[NMAX * NHEAD];
__device__ float g_adst[NMAX * NHEAD];
__device__ int   g_rowptr[NMAX + 1];
__device__ int   g_deg[NMAX];
__device__ int   g_cursor[NMAX];
__device__ int   g_csrc[EMAX];

// ---------------- helpers ---------------------------------------------------
static __device__ __forceinline__ float leaky(float x) { return fmaxf(x, 0.2f * x); }
static __device__ __forceinline__ float sel4(float4 v, int h) {
    return h == 0 ? v.x : (h == 1 ? v.y : (h == 2 ? v.z : v.w));
}

// ---------------- CSR build --------------------------------------------------
__global__ void zero2_kernel(int* a, int* b, int n) {
    int i = blockIdx.x * blockDim.x + threadIdx.x;
    if (i < n) { a[i] = 0; b[i] = 0; }
}

__global__ void hist_kernel(const int* __restrict__ ei, int E, int* __restrict__ deg) {
    int i = blockIdx.x * blockDim.x + threadIdx.x;
    if (i < E) atomicAdd(&deg[ei[E + i]], 1);
}

__global__ void scan_kernel(const int* __restrict__ deg, int* __restrict__ rowptr, int n) {
    __shared__ int partials[1024];
    int tid = threadIdx.x;
    int per = (n + 1023) >> 10;
    int start = tid * per;
    int end = min(start + per, n);
    int s = 0;
    for (int i = start; i < end; i++) s += deg[i];
    partials[tid] = s;
    __syncthreads();
    for (int d = 1; d < 1024; d <<= 1) {
        int v = (tid >= d) ? partials[tid - d] : 0;
        __syncthreads();
        partials[tid] += v;
        __syncthreads();
    }
    int run = partials[tid] - s;  // exclusive prefix
    for (int i = start; i < end; i++) { rowptr[i] = run; run += deg[i]; }
    if (end == n) rowptr[n] = run;
}

__global__ void scatter_kernel(const int* __restrict__ ei, int E,
                               const int* __restrict__ rowptr,
                               int* __restrict__ cursor, int* __restrict__ csrc) {
    int i = blockIdx.x * blockDim.x + threadIdx.x;
    if (i < E) {
        int d = ei[E + i];
        int pos = atomicAdd(&cursor[d], 1);
        csrc[rowptr[d] + pos] = ei[i];
    }
}

// ---------------- fp32 tiled GEMM: C[M,Nn] = A[M,K] @ B[K,Nn] ----------------
#define BM 128
#define BN 64
#define BK 16
#define ASTRIDE 132

__global__ __launch_bounds__(256) void gemm_kernel(const float* __restrict__ A,
                                                   const float* __restrict__ B,
                                                   float* __restrict__ C,
                                                   int M, int K, int Nn) {
    __shared__ float As[BK * ASTRIDE];
    __shared__ float Bs[BK * BN];
    const int t = threadIdx.x;
    const int tx = t & 15, ty = t >> 4;
    const int m0 = blockIdx.x * BM, n0 = blockIdx.y * BN;
    float acc[8][4];
#pragma unroll
    for (int i = 0; i < 8; i++)
#pragma unroll
        for (int j = 0; j < 4; j++) acc[i][j] = 0.f;

    for (int kt = 0; kt < K; kt += BK) {
#pragma unroll
        for (int L = 0; L < 2; L++) {
            int f = t + L * 256;
            int row = f >> 2;
            int kg = (f & 3) << 2;
            float4 av = make_float4(0.f, 0.f, 0.f, 0.f);
            int m = m0 + row;
            if (m < M) av = *(const float4*)(A + (size_t)m * K + kt + kg);
            As[(kg + 0) * ASTRIDE + row] = av.x;
            As[(kg + 1) * ASTRIDE + row] = av.y;
            As[(kg + 2) * ASTRIDE + row] = av.z;
            As[(kg + 3) * ASTRIDE + row] = av.w;
        }
        {
            int row = t >> 4;
            int cg = (t & 15) << 2;
            float4 bv = *(const float4*)(B + (size_t)(kt + row) * Nn + n0 + cg);
            *(float4*)(Bs + row * BN + cg) = bv;
        }
        __syncthreads();
#pragma unroll
        for (int kk = 0; kk < BK; kk++) {
            float4 a0 = *(const float4*)(As + kk * ASTRIDE + ty * 8);
            float4 a1 = *(const float4*)(As + kk * ASTRIDE + ty * 8 + 4);
            float4 b0 = *(const float4*)(Bs + kk * BN + tx * 4);
            float a[8] = {a0.x, a0.y, a0.z, a0.w, a1.x, a1.y, a1.z, a1.w};
            float b[4] = {b0.x, b0.y, b0.z, b0.w};
#pragma unroll
            for (int i = 0; i < 8; i++)
#pragma unroll
                for (int j = 0; j < 4; j++) acc[i][j] = fmaf(a[i], b[j], acc[i][j]);
        }
        __syncthreads();
    }
#pragma unroll
    for (int i = 0; i < 8; i++) {
        int m = m0 + ty * 8 + i;
        if (m < M)
            *(float4*)(C + (size_t)m * Nn + n0 + tx * 4) =
                make_float4(acc[i][0], acc[i][1], acc[i][2], acc[i][3]);
    }
}

// ---------------- attention coefficients: a_src/a_dst [N,4] ------------------
__global__ __launch_bounds__(256) void att_kernel(const float* __restrict__ hbuf,
                                                  const float* __restrict__ att_s,
                                                  const float* __restrict__ att_d,
                                                  float* __restrict__ asrc,
                                                  float* __restrict__ adst, int N) {
    int gw = (blockIdx.x * blockDim.x + threadIdx.x) >> 5;
    int lane = threadIdx.x & 31;
    if (gw >= N) return;
    int c = lane * 8;
    float4 h0 = *(const float4*)(hbuf + (size_t)gw * HC + c);
    float4 h1 = *(const float4*)(hbuf + (size_t)gw * HC + c + 4);
    float4 s0 = *(const float4*)(att_s + c);
    float4 s1 = *(const float4*)(att_s + c + 4);
    float4 d0 = *(const float4*)(att_d + c);
    float4 d1 = *(const float4*)(att_d + c + 4);
    float ps = h0.x * s0.x + h0.y * s0.y + h0.z * s0.z + h0.w * s0.w +
               h1.x * s1.x + h1.y * s1.y + h1.z * s1.z + h1.w * s1.w;
    float pd = h0.x * d0.x + h0.y * d0.y + h0.z * d0.z + h0.w * d0.w +
               h1.x * d1.x + h1.y * d1.y + h1.z * d1.z + h1.w * d1.w;
#pragma unroll
    for (int o = 1; o < 8; o <<= 1) {
        ps += __shfl_xor_sync(FULLMASK, ps, o);
        pd += __shfl_xor_sync(FULLMASK, pd, o);
    }
    if ((lane & 7) == 0) {
        int head = lane >> 3;
        asrc[gw * 4 + head] = ps;
        adst[gw * 4 + head] = pd;
    }
}

// ---------------- per-node aggregation core (phases 1-3) ---------------------
// Returns acc0/acc1 = sum over incoming edges of alpha * h[src][lane*8 .. +7].
static __device__ __forceinline__ void agg_core(const float* __restrict__ hbuf,
                                                const float* __restrict__ asrc,
                                                const float* __restrict__ adst,
                                                const int* __restrict__ rowptr,
                                                const int* __restrict__ csrc,
                                                int gw, int lane,
                                                float4& acc0, float4& acc1) {
    int hsel = lane >> 3;
    int beg = rowptr[gw], end = rowptr[gw + 1];
    float4 ad = *(const float4*)(adst + gw * 4);

    // phase 1: segment max (per head), all 4 heads per lane
    float4 mx = make_float4(-1e30f, -1e30f, -1e30f, -1e30f);
    for (int j = beg + lane; j < end; j += 32) {
        int s = csrc[j];
        float4 as = *(const float4*)(asrc + s * 4);
        mx.x = fmaxf(mx.x, leaky(as.x + ad.x));
        mx.y = fmaxf(mx.y, leaky(as.y + ad.y));
        mx.z = fmaxf(mx.z, leaky(as.z + ad.z));
        mx.w = fmaxf(mx.w, leaky(as.w + ad.w));
    }
#pragma unroll
    for (int o = 16; o; o >>= 1) {
        mx.x = fmaxf(mx.x, __shfl_xor_sync(FULLMASK, mx.x, o));
        mx.y = fmaxf(mx.y, __shfl_xor_sync(FULLMASK, mx.y, o));
        mx.z = fmaxf(mx.z, __shfl_xor_sync(FULLMASK, mx.z, o));
        mx.w = fmaxf(mx.w, __shfl_xor_sync(FULLMASK, mx.w, o));
    }

    // phase 2: exp-sum
    float4 sm = make_float4(0.f, 0.f, 0.f, 0.f);
    for (int j = beg + lane; j < end; j += 32) {
        int s = csrc[j];
        float4 as = *(const float4*)(asrc + s * 4);
        sm.x += __expf(leaky(as.x + ad.x) - mx.x);
        sm.y += __expf(leaky(as.y + ad.y) - mx.y);
        sm.z += __expf(leaky(as.z + ad.z) - mx.z);
        sm.w += __expf(leaky(as.w + ad.w) - mx.w);
    }
#pragma unroll
    for (int o = 16; o; o >>= 1) {
        sm.x += __shfl_xor_sync(FULLMASK, sm.x, o);
        sm.y += __shfl_xor_sync(FULLMASK, sm.y, o);
        sm.z += __shfl_xor_sync(FULLMASK, sm.z, o);
        sm.w += __shfl_xor_sync(FULLMASK, sm.w, o);
    }
    float4 inv = make_float4(1.f / (sm.x + 1e-16f), 1.f / (sm.y + 1e-16f),
                             1.f / (sm.z + 1e-16f), 1.f / (sm.w + 1e-16f));
    float mh = sel4(mx, hsel), ih = sel4(inv, hsel), adh = sel4(ad, hsel);

    // phase 3: weighted gather-accumulate (whole warp walks each edge)
    acc0 = make_float4(0.f, 0.f, 0.f, 0.f);
    acc1 = make_float4(0.f, 0.f, 0.f, 0.f);
    const int cbase = lane * 8;
    for (int j = beg; j < end; j++) {
        int s = csrc[j];
        float as = asrc[s * 4 + hsel];
        float alpha = __expf(leaky(as + adh) - mh) * ih;
        const float4* hp = (const float4*)(hbuf + (size_t)s * HC + cbase);
        float4 v0 = hp[0], v1 = hp[1];
        acc0.x = fmaf(v0.x, alpha, acc0.x);
        acc0.y = fmaf(v0.y, alpha, acc0.y);
        acc0.z = fmaf(v0.z, alpha, acc0.z);
        acc0.w = fmaf(v0.w, alpha, acc0.w);
        acc1.x = fmaf(v1.x, alpha, acc1.x);
        acc1.y = fmaf(v1.y, alpha, acc1.y);
        acc1.z = fmaf(v1.z, alpha, acc1.z);
        acc1.w = fmaf(v1.w, alpha, acc1.w);
    }
}

// layer 1: concat=True epilogue (bias + relu -> [N,256])
__global__ __launch_bounds__(256) void agg1_kernel(const float* __restrict__ hbuf,
                                                   const float* __restrict__ asrc,
                                                   const float* __restrict__ adst,
                                                   const int* __restrict__ rowptr,
                                                   const int* __restrict__ csrc,
                                                   const float* __restrict__ bias,
                                                   float* __restrict__ outbuf, int N) {
    int gw = (blockIdx.x * blockDim.x + threadIdx.x) >> 5;
    int lane = threadIdx.x & 31;
    if (gw >= N) return;
    float4 acc0, acc1;
    agg_core(hbuf, asrc, adst, rowptr, csrc, gw, lane, acc0, acc1);
    int cbase = lane * 8;
    float4 b0 = *(const float4*)(bias + cbase);
    float4 b1 = *(const float4*)(bias + cbase + 4);
    float* op = outbuf + (size_t)gw * HC + cbase;
    ((float4*)op)[0] = make_float4(fmaxf(acc0.x + b0.x, 0.f), fmaxf(acc0.y + b0.y, 0.f),
                                   fmaxf(acc0.z + b0.z, 0.f), fmaxf(acc0.w + b0.w, 0.f));
    ((float4*)op)[1] = make_float4(fmaxf(acc1.x + b1.x, 0.f), fmaxf(acc1.y + b1.y, 0.f),
                                   fmaxf(acc1.z + b1.z, 0.f), fmaxf(acc1.w + b1.w, 0.f));
}

// layer 2: head-mean + bias + relu + softmax(64) -> [N,64]
__global__ __launch_bounds__(256) void agg2_kernel(const float* __restrict__ hbuf,
                                                   const float* __restrict__ asrc,
                                                   const float* __restrict__ adst,
                                                   const int* __restrict__ rowptr,
                                                   const int* __restrict__ csrc,
                                                   const float* __restrict__ bias,
                                                   float* __restrict__ outp, int N) {
    int gw = (blockIdx.x * blockDim.x + threadIdx.x) >> 5;
    int lane = threadIdx.x & 31;
    if (gw >= N) return;
    float4 acc0, acc1;
    agg_core(hbuf, asrc, adst, rowptr, csrc, gw, lane, acc0, acc1);

    float r[8] = {acc0.x, acc0.y, acc0.z, acc0.w, acc1.x, acc1.y, acc1.z, acc1.w};
    // sum across heads: lanes {l, l^8, l^16, l^24} hold the same within-head channel
#pragma unroll
    for (int k = 0; k < 8; k++) {
        r[k] += __shfl_xor_sync(FULLMASK, r[k], 8);
        r[k] += __shfl_xor_sync(FULLMASK, r[k], 16);
    }
    int cp = (lane & 7) * 8;  // within-head channel base
    float4 b0 = *(const float4*)(bias + cp);
    float4 b1 = *(const float4*)(bias + cp + 4);
    float bb[8] = {b0.x, b0.y, b0.z, b0.w, b1.x, b1.y, b1.z, b1.w};
    float lm = -1e30f;
#pragma unroll
    for (int k = 0; k < 8; k++) {
        r[k] = fmaxf(0.25f * r[k] + bb[k], 0.f);  // mean over 4 heads, +bias, relu
        lm = fmaxf(lm, r[k]);
    }
#pragma unroll
    for (int o = 4; o; o >>= 1) lm = fmaxf(lm, __shfl_xor_sync(FULLMASK, lm, o));
    float ls = 0.f;
#pragma unroll
    for (int k = 0; k < 8; k++) { r[k] = __expf(r[k] - lm); ls += r[k]; }
#pragma unroll
    for (int o = 4; o; o >>= 1) ls += __shfl_xor_sync(FULLMASK, ls, o);
    float invs = 1.f / ls;
    if (lane < 8) {
        float* op = outp + (size_t)gw * CH + lane * 8;
        ((float4*)op)[0] = make_float4(r[0] * invs, r[1] * invs, r[2] * invs, r[3] * invs);
        ((float4*)op)[1] = make_float4(r[4] * invs, r[5] * invs, r[6] * invs, r[7] * invs);
    }
}

// ---------------- launch -----------------------------------------------------
extern "C" void kernel_launch(void* const* d_in, const int* in_sizes, int n_in,
                              void* d_out, int out_size) {
    const float* x   = (const float*)d_in[0];
    const int*   ei  = (const int*)d_in[1];
    const float* W1  = (const float*)d_in[2];
    const float* as1 = (const float*)d_in[3];
    const float* ad1 = (const float*)d_in[4];
    const float* b1  = (const float*)d_in[5];
    const float* W2  = (const float*)d_in[6];
    const float* as2 = (const float*)d_in[7];
    const float* ad2 = (const float*)d_in[8];
    const float* b2  = (const float*)d_in[9];
    float* out = (float*)d_out;

    const int N = in_sizes[0] / DIN;
    const int E = in_sizes[1] / 2;

    float *dH, *dAct, *dAs, *dAd;
    int *dRow, *dDeg, *dCur, *dCsr;
    cudaGetSymbolAddress((void**)&dH, g_h);
    cudaGetSymbolAddress((void**)&dAct, g_act);
    cudaGetSymbolAddress((void**)&dAs, g_asrc);
    cudaGetSymbolAddress((void**)&dAd, g_adst);
    cudaGetSymbolAddress((void**)&dRow, g_rowptr);
    cudaGetSymbolAddress((void**)&dDeg, g_deg);
    cudaGetSymbolAddress((void**)&dCur, g_cursor);
    cudaGetSymbolAddress((void**)&dCsr, g_csrc);

    // CSR build (by destination node)
    zero2_kernel<<<(N + 255) / 256, 256>>>(dDeg, dCur, N);
    hist_kernel<<<(E + 255) / 256, 256>>>(ei, E, dDeg);
    scan_kernel<<<1, 1024>>>(dDeg, dRow, N);
    scatter_kernel<<<(E + 255) / 256, 256>>>(ei, E, dRow, dCur, dCsr);

    const int warpBlocks = (N * 32 + 255) / 256;
    dim3 gg((N + BM - 1) / BM, HC / BN);

    // layer 1
    gemm_kernel<<<gg, 256>>>(x, W1, dH, N, DIN, HC);
    att_kernel<<<warpBlocks, 256>>>(dH, as1, ad1, dAs, dAd, N);
    agg1_kernel<<<warpBlocks, 256>>>(dH, dAs, dAd, dRow, dCsr, b1, dAct, N);

    // layer 2
    gemm_kernel<<<gg, 256>>>(dAct, W2, dH, N, HC, HC);
    att_kernel<<<warpBlocks, 256>>>(dH, as2, ad2, dAs, dAd, N);
    agg2_kernel<<<warpBlocks, 256>>>(dH, dAs, dAd, dRow, dCsr, b2, out, N);
}